// round 10
// baseline (speedup 1.0000x reference)
#include <cuda_runtime.h>
#include <cuda_fp16.h>
#include <cstdint>
#include <cstddef>

#define B_   2048
#define NIN  64
#define D_   128
#define RANK 24
#define KFM  1536   // NIN*RANK
#define HID  1024
#define N3   4096   // N_FMB*D

// ---- scratch (static device globals; no runtime allocation) ----
__device__ __half g_fmn[B_ * KFM];     // normalized FM features (half)
__device__ __half g_h1 [B_ * HID];
__device__ __half g_h2 [B_ * HID];
__device__ __half g_w1t[HID * KFM];    // w^T [N,K] half
__device__ __half g_w2t[HID * HID];
__device__ __half g_w3t[N3  * HID];

// ============================================================================
// helpers
// ============================================================================
__device__ __forceinline__ uint32_t smem_u32(const void* p) {
    uint32_t a;
    asm("{ .reg .u64 t; cvta.to.shared.u64 t, %1; cvt.u32.u64 %0, t; }" : "=r"(a) : "l"(p));
    return a;
}
__device__ __forceinline__ void cpasync16(uint32_t dst, const void* src) {
    asm volatile("cp.async.cg.shared.global [%0], [%1], 16;" :: "r"(dst), "l"(src));
}
__device__ __forceinline__ void ldmx4(uint32_t addr, uint32_t& r0, uint32_t& r1,
                                      uint32_t& r2, uint32_t& r3) {
    asm volatile("ldmatrix.sync.aligned.m8n8.x4.shared.b16 {%0,%1,%2,%3}, [%4];"
                 : "=r"(r0), "=r"(r1), "=r"(r2), "=r"(r3) : "r"(addr));
}
__device__ __forceinline__ void ldmx4t(uint32_t addr, uint32_t& r0, uint32_t& r1,
                                       uint32_t& r2, uint32_t& r3) {
    asm volatile("ldmatrix.sync.aligned.m8n8.x4.trans.shared.b16 {%0,%1,%2,%3}, [%4];"
                 : "=r"(r0), "=r"(r1), "=r"(r2), "=r"(r3) : "r"(addr));
}
// fp16 mma with fp32 accumulators: m16n8k16
#define MMA_F16(acc, a, b)                                                      \
    asm volatile("mma.sync.aligned.m16n8k16.row.col.f32.f16.f16.f32 "           \
        "{%0,%1,%2,%3}, {%4,%5,%6,%7}, {%8,%9}, {%0,%1,%2,%3};"                 \
        : "+f"((acc)[0]), "+f"((acc)[1]), "+f"((acc)[2]), "+f"((acc)[3])        \
        : "r"((a)[0]), "r"((a)[1]), "r"((a)[2]), "r"((a)[3]),                   \
          "r"((b)[0]), "r"((b)[1]))

// ============================================================================
// k_tr: Dst[N,K] = half(Src[K,N]^T).  32x32 tiles, block (16,16).
// ============================================================================
__global__ __launch_bounds__(256) void k_tr(const float* __restrict__ S,
                                            __half* __restrict__ Dst, int K, int N)
{
    __shared__ float t[32][33];
    const int k0 = blockIdx.y * 32, n0 = blockIdx.x * 32;
    const int tx = threadIdx.x, ty = threadIdx.y;   // 16 x 16
    #pragma unroll
    for (int i = 0; i < 2; i++) {
        float2 v = *(const float2*)&S[(size_t)(k0 + ty + i * 16) * N + n0 + 2 * tx];
        t[ty + i * 16][2 * tx]     = v.x;
        t[ty + i * 16][2 * tx + 1] = v.y;
    }
    __syncthreads();
    #pragma unroll
    for (int i = 0; i < 2; i++) {
        const int n = n0 + ty + i * 16;
        __half2 h = __floats2half2_rn(t[2 * tx][ty + i * 16], t[2 * tx + 1][ty + i * 16]);
        *(__half2*)&Dst[(size_t)n * K + k0 + 2 * tx] = h;
    }
}

// ============================================================================
// k_fm: per-batch FM (Gram trick) + lcb on fp16 mma; fused LN rows 32-63.
// Phase order tuned for register lifetime: G mma -> fm/LN -> lcb mma -> row LN.
// ============================================================================
#define FM_XH_STR 136
#define FM_GSTR   66
#define FM_OFF_WR  (64 * FM_GSTR)            // 4224
#define FM_OFF_RED (FM_OFF_WR + KFM)         // 5760
#define FM_OFF_XH  (FM_OFF_RED + 32)         // 5792 (byte 23168, 16B aligned)
#define FM_XH_BYTES (64 * FM_XH_STR * 2)     // 17408
#define FM_WL_BYTES (64 * 40 * 2)            // 5120
#define FM_SMEM (FM_OFF_XH * 4 + FM_XH_BYTES + FM_WL_BYTES)   // 45696 B

__global__ __launch_bounds__(256, 4) void k_fm(const float* __restrict__ x,
                                               const float* __restrict__ wr,
                                               const float* __restrict__ wl,
                                               const float* __restrict__ gamma,
                                               const float* __restrict__ beta,
                                               float* __restrict__ out)
{
    extern __shared__ float Sf[];
    float*  Gs   = Sf;                                   // 64 x 66
    float*  ws   = Sf + FM_OFF_WR;                       // 64 x 24
    float*  red  = Sf + FM_OFF_RED;                      // 32
    __half* xs_h = (__half*)(Sf + FM_OFF_XH);            // 64 x 136
    __half* wl_h = (__half*)((char*)(Sf + FM_OFF_XH) + FM_XH_BYTES);  // 64 x 40

    const int b = blockIdx.x, tid = threadIdx.x;
    const int lane = tid & 31, warp = tid >> 5;
    const int gid = lane >> 2, tig = lane & 3;

    // ---- phase 1: load x -> half smem; wr -> fp32; wl -> half [k][m] ----
    {
        const float4* xg = (const float4*)(x + (size_t)b * NIN * D_);
        #pragma unroll
        for (int i = 0; i < 8; i++) {
            int v = tid + i * 256;
            float4 t = xg[v];
            int n = v >> 5, d0 = (v & 31) * 4;
            *(__half2*)&xs_h[n * FM_XH_STR + d0]     = __floats2half2_rn(t.x, t.y);
            *(__half2*)&xs_h[n * FM_XH_STR + d0 + 2] = __floats2half2_rn(t.z, t.w);
        }
        const float4* wg = (const float4*)wr;
        ((float4*)ws)[tid] = wg[tid];
        if (tid < 128) ((float4*)ws)[256 + tid] = wg[256 + tid];
        const float4* wlg = (const float4*)wl;
        #pragma unroll
        for (int i = 0; i < 2; i++) {
            int idx = tid + i * 256;
            float4 t = wlg[idx];
            int nn = idx >> 3, m0 = (idx & 7) * 4;
            *(__half2*)&wl_h[nn * 40 + m0]     = __floats2half2_rn(t.x, t.y);
            *(__half2*)&wl_h[nn * 40 + m0 + 2] = __floats2half2_rn(t.z, t.w);
        }
    }
    __syncthreads();

    // ---- phase 2: G = x @ x^T (8 warps = 4m x 2n, warp tile 16x32) ----
    const uint32_t xb = smem_u32(xs_h);
    {
        const int wm = warp >> 1, wn = warp & 1;
        const uint32_t abase = xb + (((16 * wm + (lane & 15)) * FM_XH_STR) + (lane >> 4) * 8) * 2;
        const int nrow_l = (lane & 7) + 8 * (lane >> 4);
        const int kofs_l = ((lane >> 3) & 1) * 8;
        uint32_t bbase[2];
        #pragma unroll
        for (int p = 0; p < 2; p++)
            bbase[p] = xb + (((32 * wn + p * 16 + nrow_l) * FM_XH_STR) + kofs_l) * 2;

        float acc[4][4];
        #pragma unroll
        for (int i = 0; i < 4; i++)
            #pragma unroll
            for (int q = 0; q < 4; q++) acc[i][q] = 0.f;

        #pragma unroll
        for (int kk = 0; kk < 8; kk++) {
            const uint32_t off = kk * 32;
            uint32_t a[4], bf[4][2];
            ldmx4(abase + off, a[0], a[1], a[2], a[3]);
            #pragma unroll
            for (int p = 0; p < 2; p++)
                ldmx4(bbase[p] + off,
                      bf[2 * p][0], bf[2 * p][1], bf[2 * p + 1][0], bf[2 * p + 1][1]);
            #pragma unroll
            for (int nt = 0; nt < 4; nt++) MMA_F16(acc[nt], a, bf[nt]);
        }
        #pragma unroll
        for (int nt = 0; nt < 4; nt++) {
            const int col = 32 * wn + nt * 8 + 2 * tig;
            *(float2*)&Gs[(16 * wm + gid) * FM_GSTR + col]     = make_float2(acc[nt][0], acc[nt][1]);
            *(float2*)&Gs[(16 * wm + 8 + gid) * FM_GSTR + col] = make_float2(acc[nt][2], acc[nt][3]);
        }
    }
    __syncthreads();

    // ---- phase 3: fm = G @ w (fp32, ms-split), LN, store half ----
    {
        const int jq = tid & 3, ms = (tid >> 2) & 3, ng = tid >> 4;
        const int j0 = jq * 6;
        float f[4][6];
        #pragma unroll
        for (int i = 0; i < 4; i++)
            #pragma unroll
            for (int j = 0; j < 6; j++) f[i][j] = 0.f;

        #pragma unroll 4
        for (int mm = 0; mm < 16; mm++) {
            const int m = mm * 4 + ms;
            const float* wrow = ws + m * 24 + j0;
            float2 wa = *(const float2*)(wrow);
            float2 wb = *(const float2*)(wrow + 2);
            float2 wc = *(const float2*)(wrow + 4);
            float wv[6] = {wa.x, wa.y, wb.x, wb.y, wc.x, wc.y};
            #pragma unroll
            for (int i = 0; i < 4; i++) {
                float g = Gs[(4 * ng + i) * FM_GSTR + m];
                #pragma unroll
                for (int j = 0; j < 6; j++) f[i][j] += g * wv[j];
            }
        }
        float lsum = 0.f, lsq = 0.f;
        #pragma unroll
        for (int i = 0; i < 4; i++)
            #pragma unroll
            for (int j = 0; j < 6; j++) {
                float v = f[i][j];
                v += __shfl_xor_sync(0xFFFFFFFFu, v, 4);
                v += __shfl_xor_sync(0xFFFFFFFFu, v, 8);
                f[i][j] = v;
                if (ms == 0) { lsum += v; lsq += v * v; }
            }
        #pragma unroll
        for (int o = 16; o > 0; o >>= 1) {
            lsum += __shfl_xor_sync(0xFFFFFFFFu, lsum, o);
            lsq  += __shfl_xor_sync(0xFFFFFFFFu, lsq,  o);
        }
        if (lane == 0) { red[warp] = lsum; red[8 + warp] = lsq; }
        __syncthreads();                      // also: all Gs reads complete
        if (tid == 0) {
            float s = 0.f, q = 0.f;
            #pragma unroll
            for (int i = 0; i < 8; i++) { s += red[i]; q += red[8 + i]; }
            float mu  = s * (1.f / KFM);
            float var = q * (1.f / KFM) - mu * mu;
            float sd  = sqrtf(fmaxf(var, 0.f));
            sd = fminf(fmaxf(sd, 1e-11f), 1e7f);
            red[16] = mu;
            red[17] = 1.f / sd;
        }
        __syncthreads();
        const float mu = red[16], inv = red[17];

        if (ms == 0) {
            __half* o = g_fmn + (size_t)b * KFM;
            #pragma unroll
            for (int i = 0; i < 4; i++) {
                __half* op = o + (4 * ng + i) * 24 + j0;
                #pragma unroll
                for (int j = 0; j < 6; j += 2)
                    *(__half2*)(op + j) =
                        __floats2half2_rn((f[i][j] - mu) * inv, (f[i][j + 1] - mu) * inv);
            }
        }
    }

    // ---- phase 4: lcb = wl^T @ x (8 warps = 2m x 4n), stage into Gs, LN ----
    {
        float lacc[4][4];
        const int wm2 = warp >> 2, wn2 = warp & 3;
        #pragma unroll
        for (int i = 0; i < 4; i++)
            #pragma unroll
            for (int q = 0; q < 4; q++) lacc[i][q] = 0.f;

        const uint32_t wlb = smem_u32(wl_h);
        const uint32_t a_addr = wlb +
            (((lane & 7) + 8 * ((lane >> 4) & 1)) * 40 + 16 * wm2 + 8 * ((lane >> 3) & 1)) * 2;
        const int kofB = (lane & 7) + 8 * ((lane >> 3) & 1);
        const int nofB = 8 * (lane >> 4);
        uint32_t b_addr[2];
        #pragma unroll
        for (int p = 0; p < 2; p++)
            b_addr[p] = xb + (kofB * FM_XH_STR + 32 * wn2 + 16 * p + nofB) * 2;

        #pragma unroll
        for (int kk = 0; kk < 4; kk++) {
            uint32_t a[4], bf[4][2];
            ldmx4t(a_addr + kk * 16 * 40 * 2, a[0], a[1], a[2], a[3]);
            #pragma unroll
            for (int p = 0; p < 2; p++)
                ldmx4t(b_addr[p] + kk * 16 * FM_XH_STR * 2,
                       bf[2 * p][0], bf[2 * p][1], bf[2 * p + 1][0], bf[2 * p + 1][1]);
            #pragma unroll
            for (int nt = 0; nt < 4; nt++) MMA_F16(lacc[nt], a, bf[nt]);
        }

        float* Ls = Gs;     // Gs free after phase 3's first barrier
        #pragma unroll
        for (int nt = 0; nt < 4; nt++) {
            const int col = 32 * wn2 + nt * 8 + 2 * tig;
            *(float2*)&Ls[(16 * wm2 + gid) * 132 + col]     = make_float2(lacc[nt][0], lacc[nt][1]);
            *(float2*)&Ls[(16 * wm2 + 8 + gid) * 132 + col] = make_float2(lacc[nt][2], lacc[nt][3]);
        }
    }
    __syncthreads();

    {
        const float4 g4 = __ldg((const float4*)gamma + lane);
        const float4 bt = __ldg((const float4*)beta  + lane);
        float* ob = out + (size_t)b * NIN * D_;
        const float* Ls = Gs;
        #pragma unroll
        for (int i = 0; i < 4; i++) {
            const int sr = warp * 4 + i;          // staged row 0..31
            const int r  = 32 + sr;               // out row
            float4 v  = *(const float4*)&Ls[sr * 132 + lane * 4];
            float4 xr = __ldg((const float4*)(x + (size_t)b * NIN * D_ + r * D_ + lane * 4));
            float4 p = make_float4(v.x + xr.x, v.y + xr.y, v.z + xr.z, v.w + xr.w);
            float s = p.x + p.y + p.z + p.w;
            float q = p.x * p.x + p.y * p.y + p.z * p.z + p.w * p.w;
            #pragma unroll
            for (int o = 16; o > 0; o >>= 1) {
                s += __shfl_xor_sync(0xFFFFFFFFu, s, o);
                q += __shfl_xor_sync(0xFFFFFFFFu, q, o);
            }
            float mean = s * (1.f / 128.f);
            float var  = q * (1.f / 128.f) - mean * mean;
            float invs = rsqrtf(var + 1e-3f);
            float4 o4;
            o4.x = (p.x - mean) * invs * g4.x + bt.x;
            o4.y = (p.y - mean) * invs * g4.y + bt.y;
            o4.z = (p.z - mean) * invs * g4.z + bt.z;
            o4.w = (p.w - mean) * invs * g4.w + bt.w;
            *(float4*)(ob + r * D_ + lane * 4) = o4;
        }
    }
}

// ============================================================================
// k_mm: fp16 mma.sync GEMM (m16n8k16), ldmatrix b16 fragments.
// M64 x N128 x K64 CTA tile, 8 warps (2x4), warp tile 32x32,
// double-buffered cp.async, stride 72 halves, 4 CTAs/SM.
// ============================================================================
#define MM_HSTR 72
#define MM_A_TILEB (64 * MM_HSTR * 2)    // 9216 B
#define MM_B_TILEB (128 * MM_HSTR * 2)   // 18432 B
#define MM_STGB  (MM_A_TILEB + MM_B_TILEB)   // 27648 B per stage
#define K_MM_SMEM (2 * MM_STGB)              // 55296 B

struct MMCtx {
    uint32_t aoff[2];
    uint32_t boff[2];
    int wr, wc, gid, tig;
};
__device__ __forceinline__ void mm_setup(MMCtx& c, uint32_t sbase, int tid) {
    const int lane = tid & 31, wid = tid >> 5;
    c.wr = wid >> 2; c.wc = wid & 3;
    c.gid = lane >> 2; c.tig = lane & 3;
    #pragma unroll
    for (int mt = 0; mt < 2; mt++)
        c.aoff[mt] = sbase + (((c.wr * 32 + mt * 16 + (lane & 15)) * MM_HSTR) + (lane >> 4) * 8) * 2;
    const int nrow_l = (lane & 7) + 8 * (lane >> 4);
    const int kofs_l = ((lane >> 3) & 1) * 8;
    #pragma unroll
    for (int p = 0; p < 2; p++)
        c.boff[p] = sbase + MM_A_TILEB + (((c.wc * 32 + p * 16 + nrow_l) * MM_HSTR) + kofs_l) * 2;
}
__device__ __forceinline__ void mm_mainloop(const MMCtx& c, uint32_t sbase, int tid,
                                            const __half* A, const __half* Wt,
                                            int brow, int bcol, int K,
                                            float acc[2][4][4]) {
    auto load_stage = [&](int s, int kc) {
        const uint32_t As = sbase + s * MM_STGB;
        const uint32_t Bs = As + MM_A_TILEB;
        const __half* Ag = A  + (size_t)brow * K + kc * 64;
        const __half* Bg = Wt + (size_t)bcol * K + kc * 64;
        #pragma unroll
        for (int i = 0; i < 2; i++) {                 // A: 64 rows x 8 chunks
            int v = tid + i * 256;
            int r = v >> 3, ch = (v & 7) * 8;
            cpasync16(As + (r * MM_HSTR + ch) * 2, Ag + (size_t)r * K + ch);
        }
        #pragma unroll
        for (int i = 0; i < 4; i++) {                 // B: 128 rows x 8 chunks
            int v = tid + i * 256;
            int r = v >> 3, ch = (v & 7) * 8;
            cpasync16(Bs + (r * MM_HSTR + ch) * 2, Bg + (size_t)r * K + ch);
        }
    };
    const int NK = K >> 6;
    load_stage(0, 0);
    asm volatile("cp.async.commit_group;");
    for (int kc = 0; kc < NK; kc++) {
        const int buf = kc & 1;
        if (kc + 1 < NK) {
            load_stage(buf ^ 1, kc + 1);
            asm volatile("cp.async.commit_group;");
            asm volatile("cp.async.wait_group 1;");
        } else {
            asm volatile("cp.async.wait_group 0;");
        }
        __syncthreads();
        const uint32_t so = buf * MM_STGB;
        #pragma unroll
        for (int kk = 0; kk < 4; kk++) {
            const uint32_t off = so + kk * 32;
            uint32_t a[2][4], bf[4][2];
            #pragma unroll
            for (int mt = 0; mt < 2; mt++)
                ldmx4(c.aoff[mt] + off, a[mt][0], a[mt][1], a[mt][2], a[mt][3]);
            #pragma unroll
            for (int p = 0; p < 2; p++)
                ldmx4(c.boff[p] + off,
                      bf[2 * p][0], bf[2 * p][1], bf[2 * p + 1][0], bf[2 * p + 1][1]);
            #pragma unroll
            for (int mt = 0; mt < 2; mt++)
                #pragma unroll
                for (int nt = 0; nt < 4; nt++) MMA_F16(acc[mt][nt], a[mt], bf[nt]);
        }
        __syncthreads();
    }
}

__global__ __launch_bounds__(256, 4) void k_mm_relu(const __half* __restrict__ A,
                                                    const __half* __restrict__ Wt,
                                                    __half* __restrict__ C,
                                                    int K, int N)
{
    extern __shared__ char smraw[];
    const uint32_t sbase = smem_u32(smraw);
    const int tid = threadIdx.x;
    const int brow = blockIdx.y * 64, bcol = blockIdx.x * 128;
    MMCtx c; mm_setup(c, sbase, tid);
    float acc[2][4][4];
    #pragma unroll
    for (int i = 0; i < 2; i++)
        #pragma unroll
        for (int j = 0; j < 4; j++)
            #pragma unroll
            for (int q = 0; q < 4; q++) acc[i][j][q] = 0.f;
    mm_mainloop(c, sbase, tid, A, Wt, brow, bcol, K, acc);
    #pragma unroll
    for (int mt = 0; mt < 2; mt++) {
        const int row = brow + c.wr * 32 + mt * 16 + c.gid;
        #pragma unroll
        for (int nt = 0; nt < 4; nt++) {
            const int col = bcol + c.wc * 32 + nt * 8 + 2 * c.tig;
            __half2 h0 = __floats2half2_rn(fmaxf(acc[mt][nt][0], 0.f), fmaxf(acc[mt][nt][1], 0.f));
            __half2 h1 = __floats2half2_rn(fmaxf(acc[mt][nt][2], 0.f), fmaxf(acc[mt][nt][3], 0.f));
            *(__half2*)(C + (size_t)row * N + col)       = h0;
            *(__half2*)(C + (size_t)(row + 8) * N + col) = h1;
        }
    }
}

#define LN_CSTR 132

__global__ __launch_bounds__(256, 4) void k_mm_ln(const __half* __restrict__ A,
                                                  const __half* __restrict__ Wt,
                                                  const float* __restrict__ x,
                                                  const float* __restrict__ gamma,
                                                  const float* __restrict__ beta,
                                                  float* __restrict__ out,
                                                  int K)
{
    extern __shared__ char smraw[];
    float* S = (float*)smraw;
    const uint32_t sbase = smem_u32(smraw);
    const int tid = threadIdx.x, lane = tid & 31, wid = tid >> 5;
    const int brow = blockIdx.y * 64, bcol = blockIdx.x * 128;
    MMCtx c; mm_setup(c, sbase, tid);
    float acc[2][4][4];
    #pragma unroll
    for (int i = 0; i < 2; i++)
        #pragma unroll
        for (int j = 0; j < 4; j++)
            #pragma unroll
            for (int q = 0; q < 4; q++) acc[i][j][q] = 0.f;
    mm_mainloop(c, sbase, tid, A, Wt, brow, bcol, K, acc);

    // stage acc -> smem (mainloop smem free; 64*132*4 = 33792 <= 55296)
    #pragma unroll
    for (int mt = 0; mt < 2; mt++) {
        const int r0 = c.wr * 32 + mt * 16 + c.gid;
        #pragma unroll
        for (int nt = 0; nt < 4; nt++) {
            const int col = c.wc * 32 + nt * 8 + 2 * c.tig;
            *(float2*)&S[r0 * LN_CSTR + col]       = make_float2(acc[mt][nt][0], acc[mt][nt][1]);
            *(float2*)&S[(r0 + 8) * LN_CSTR + col] = make_float2(acc[mt][nt][2], acc[mt][nt][3]);
        }
    }
    __syncthreads();

    const float4 g4 = __ldg((const float4*)gamma + lane);
    const float4 bt = __ldg((const float4*)beta  + lane);

    #pragma unroll
    for (int rr = 0; rr < 8; rr++) {
        const int r = wid * 8 + rr;
        const int b = brow + r;
        float4 v = *(const float4*)&S[r * LN_CSTR + lane * 4];
        float4 xr = __ldg((const float4*)(x + (size_t)b * NIN * D_ + bcol + lane * 4));
        float4 p = make_float4(v.x + xr.x, v.y + xr.y, v.z + xr.z, v.w + xr.w);
        float s = p.x + p.y + p.z + p.w;
        float q = p.x * p.x + p.y * p.y + p.z * p.z + p.w * p.w;
        #pragma unroll
        for (int o = 16; o > 0; o >>= 1) {
            s += __shfl_xor_sync(0xFFFFFFFFu, s, o);
            q += __shfl_xor_sync(0xFFFFFFFFu, q, o);
        }
        float mean = s * (1.f / 128.f);
        float var  = q * (1.f / 128.f) - mean * mean;
        float inv  = rsqrtf(var + 1e-3f);
        float4 o4;
        o4.x = (p.x - mean) * inv * g4.x + bt.x;
        o4.y = (p.y - mean) * inv * g4.y + bt.y;
        o4.z = (p.z - mean) * inv * g4.z + bt.z;
        o4.w = (p.w - mean) * inv * g4.w + bt.w;
        *(float4*)(out + (size_t)b * NIN * D_ + bcol + lane * 4) = o4;
    }
}

// ============================================================================
extern "C" void kernel_launch(void* const* d_in, const int* in_sizes, int n_in,
                              void* d_out, int out_size)
{
    const float* x      = (const float*)d_in[0];
    // d_in[1] = noise: only enters via 1e-10*extra -> numerically irrelevant
    const float* w_lcb  = (const float*)d_in[2];
    const float* w_rank = (const float*)d_in[3];
    const float* w1     = (const float*)d_in[4];
    const float* w2     = (const float*)d_in[5];
    const float* w3     = (const float*)d_in[6];
    const float* gamma  = (const float*)d_in[7];
    const float* beta   = (const float*)d_in[8];
    float* out = (float*)d_out;

    __half *fmn, *h1, *h2, *w1t, *w2t, *w3t;
    cudaGetSymbolAddress((void**)&fmn, g_fmn);
    cudaGetSymbolAddress((void**)&h1,  g_h1);
    cudaGetSymbolAddress((void**)&h2,  g_h2);
    cudaGetSymbolAddress((void**)&w1t, g_w1t);
    cudaGetSymbolAddress((void**)&w2t, g_w2t);
    cudaGetSymbolAddress((void**)&w3t, g_w3t);

    cudaFuncSetAttribute(k_mm_relu, cudaFuncAttributeMaxDynamicSharedMemorySize, K_MM_SMEM);
    cudaFuncSetAttribute(k_mm_ln,   cudaFuncAttributeMaxDynamicSharedMemorySize, K_MM_SMEM);
    cudaFuncSetAttribute(k_fm,      cudaFuncAttributeMaxDynamicSharedMemorySize, FM_SMEM);

    k_tr<<<dim3(HID / 32, KFM / 32), dim3(16, 16)>>>(w1, w1t, KFM, HID);
    k_tr<<<dim3(HID / 32, HID / 32), dim3(16, 16)>>>(w2, w2t, HID, HID);
    k_tr<<<dim3(N3  / 32, HID / 32), dim3(16, 16)>>>(w3, w3t, HID, N3);

    k_fm<<<B_, 256, FM_SMEM>>>(x, w_rank, w_lcb, gamma, beta, out);

    k_mm_relu<<<dim3(HID / 128, B_ / 64), 256, K_MM_SMEM>>>(fmn, w1t, h1, KFM, HID);
    k_mm_relu<<<dim3(HID / 128, B_ / 64), 256, K_MM_SMEM>>>(h1,  w2t, h2, HID, HID);
    k_mm_ln  <<<dim3(N3  / 128, B_ / 64), 256, K_MM_SMEM>>>(h2,  w3t, x, gamma, beta, out, HID);
}

// round 12
// speedup vs baseline: 1.1131x; 1.1131x over previous
#include <cuda_runtime.h>
#include <cuda_fp16.h>
#include <cstdint>
#include <cstddef>

#define B_   2048
#define NIN  64
#define D_   128
#define RANK 24
#define KFM  1536   // NIN*RANK
#define HID  1024
#define N3   4096   // N_FMB*D

// ---- scratch (static device globals; no runtime allocation) ----
__device__ __half g_fmn[B_ * KFM];     // normalized FM features (half)
__device__ __half g_h1 [B_ * HID];
__device__ __half g_h2 [B_ * HID];
__device__ __half g_w1t[HID * KFM];    // w^T [N,K] half
__device__ __half g_w2t[HID * HID];
__device__ __half g_w3t[N3  * HID];

// ============================================================================
// helpers
// ============================================================================
__device__ __forceinline__ uint32_t smem_u32(const void* p) {
    uint32_t a;
    asm("{ .reg .u64 t; cvta.to.shared.u64 t, %1; cvt.u32.u64 %0, t; }" : "=r"(a) : "l"(p));
    return a;
}
__device__ __forceinline__ void cpasync16(uint32_t dst, const void* src) {
    asm volatile("cp.async.cg.shared.global [%0], [%1], 16;" :: "r"(dst), "l"(src));
}
__device__ __forceinline__ void ldmx4(uint32_t addr, uint32_t& r0, uint32_t& r1,
                                      uint32_t& r2, uint32_t& r3) {
    asm volatile("ldmatrix.sync.aligned.m8n8.x4.shared.b16 {%0,%1,%2,%3}, [%4];"
                 : "=r"(r0), "=r"(r1), "=r"(r2), "=r"(r3) : "r"(addr));
}
__device__ __forceinline__ void ldmx4t(uint32_t addr, uint32_t& r0, uint32_t& r1,
                                       uint32_t& r2, uint32_t& r3) {
    asm volatile("ldmatrix.sync.aligned.m8n8.x4.trans.shared.b16 {%0,%1,%2,%3}, [%4];"
                 : "=r"(r0), "=r"(r1), "=r"(r2), "=r"(r3) : "r"(addr));
}
// fp16 mma with fp32 accumulators: m16n8k16
#define MMA_F16(acc, a, b)                                                      \
    asm volatile("mma.sync.aligned.m16n8k16.row.col.f32.f16.f16.f32 "           \
        "{%0,%1,%2,%3}, {%4,%5,%6,%7}, {%8,%9}, {%0,%1,%2,%3};"                 \
        : "+f"((acc)[0]), "+f"((acc)[1]), "+f"((acc)[2]), "+f"((acc)[3])        \
        : "r"((a)[0]), "r"((a)[1]), "r"((a)[2]), "r"((a)[3]),                   \
          "r"((b)[0]), "r"((b)[1]))

// ============================================================================
// k_tr: Dst[N,K] = half(Src[K,N]^T).  32x32 tiles, block (16,16).
// ============================================================================
__global__ __launch_bounds__(256) void k_tr(const float* __restrict__ S,
                                            __half* __restrict__ Dst, int K, int N)
{
    __shared__ float t[32][33];
    const int k0 = blockIdx.y * 32, n0 = blockIdx.x * 32;
    const int tx = threadIdx.x, ty = threadIdx.y;   // 16 x 16
    #pragma unroll
    for (int i = 0; i < 2; i++) {
        float2 v = *(const float2*)&S[(size_t)(k0 + ty + i * 16) * N + n0 + 2 * tx];
        t[ty + i * 16][2 * tx]     = v.x;
        t[ty + i * 16][2 * tx + 1] = v.y;
    }
    __syncthreads();
    #pragma unroll
    for (int i = 0; i < 2; i++) {
        const int n = n0 + ty + i * 16;
        __half2 h = __floats2half2_rn(t[2 * tx][ty + i * 16], t[2 * tx + 1][ty + i * 16]);
        *(__half2*)&Dst[(size_t)n * K + k0 + 2 * tx] = h;
    }
}

// ============================================================================
// k_fm: per-batch FM block, ALL matmuls on fp16 mma.
//   G   = x @ x^T       (64x64, K=128)  mma; G stored HALF [64][72]
//   lcb = wl^T @ x      (32x128, K=64)  mma (ldmatrix.trans)
//   fm  = G @ w_rank    (64x32(24), K=64) mma; w zero-padded to 32 cols
//   custom LN(1536) -> g_fmn (half);  lcb+residual+keras LN -> out rows 32..63
// ============================================================================
#define FM_XH_STR 136
#define FM_GH_STR 72
#define FM_B_GH   128
#define FM_B_WH   (FM_B_GH + 64 * FM_GH_STR * 2)     // 128 + 9216 = 9344
#define FM_B_WLH  (FM_B_WH + 64 * 40 * 2)            // 14464
#define FM_B_XH   (FM_B_WLH + 64 * 40 * 2)           // 19584
#define FM_SMEM   (FM_B_XH + 64 * FM_XH_STR * 2)     // 36992 B

__global__ __launch_bounds__(256, 4) void k_fm(const float* __restrict__ x,
                                               const float* __restrict__ wr,
                                               const float* __restrict__ wl,
                                               const float* __restrict__ gamma,
                                               const float* __restrict__ beta,
                                               float* __restrict__ out)
{
    extern __shared__ float Sf[];
    float*  red  = Sf;                                     // 32 floats
    __half* G_h  = (__half*)((char*)Sf + FM_B_GH);         // 64 x 72
    __half* w_h  = (__half*)((char*)Sf + FM_B_WH);         // 64 x 40 (cols 24-31 zero)
    __half* wl_h = (__half*)((char*)Sf + FM_B_WLH);        // 64 x 40
    __half* xs_h = (__half*)((char*)Sf + FM_B_XH);         // 64 x 136
    float*  Ls   = (float*)((char*)Sf + FM_B_XH);          // 32 x 132 (aliases xs_h)

    const int b = blockIdx.x, tid = threadIdx.x;
    const int lane = tid & 31, warp = tid >> 5;
    const int gid = lane >> 2, tig = lane & 3;

    // ---- phase 1: loads ----
    {
        const float4* xg = (const float4*)(x + (size_t)b * NIN * D_);
        #pragma unroll
        for (int i = 0; i < 8; i++) {
            int v = tid + i * 256;
            float4 t = xg[v];
            int n = v >> 5, d0 = (v & 31) * 4;
            *(__half2*)&xs_h[n * FM_XH_STR + d0]     = __floats2half2_rn(t.x, t.y);
            *(__half2*)&xs_h[n * FM_XH_STR + d0 + 2] = __floats2half2_rn(t.z, t.w);
        }
        // w_rank [64][24] -> w_h [64][40], TWO passes (384 float4 total)
        const float4* wg = (const float4*)wr;
        #pragma unroll
        for (int i = 0; i < 2; i++) {
            int idx = tid + i * 256;
            if (idx < 384) {
                float4 t = wg[idx];
                int m = idx / 6, j0 = (idx % 6) * 4;
                *(__half2*)&w_h[m * 40 + j0]     = __floats2half2_rn(t.x, t.y);
                *(__half2*)&w_h[m * 40 + j0 + 2] = __floats2half2_rn(t.z, t.w);
            }
        }
        // zero pad cols 24..31 (256 half2)
        {
            int row = tid >> 2, c = (tid & 3) * 2;
            *(__half2*)&w_h[row * 40 + 24 + c] = __floats2half2_rn(0.f, 0.f);
        }
        // w_lcb [64][32] -> wl_h [64][40]
        const float4* wlg = (const float4*)wl;   // 512 float4
        #pragma unroll
        for (int i = 0; i < 2; i++) {
            int idx = tid + i * 256;
            float4 t = wlg[idx];
            int nn = idx >> 3, m0 = (idx & 7) * 4;
            *(__half2*)&wl_h[nn * 40 + m0]     = __floats2half2_rn(t.x, t.y);
            *(__half2*)&wl_h[nn * 40 + m0 + 2] = __floats2half2_rn(t.z, t.w);
        }
    }
    __syncthreads();

    const uint32_t xb = smem_u32(xs_h);
    const uint32_t gb = smem_u32(G_h);

    // ---- phase 2a: G = x @ x^T (warps 4m x 2n, tile 16x32), store HALF ----
    {
        const int wm = warp >> 1, wn = warp & 1;
        const uint32_t abase = xb + (((16 * wm + (lane & 15)) * FM_XH_STR) + (lane >> 4) * 8) * 2;
        const int nrow_l = (lane & 7) + 8 * (lane >> 4);
        const int kofs_l = ((lane >> 3) & 1) * 8;
        uint32_t bbase[2];
        #pragma unroll
        for (int p = 0; p < 2; p++)
            bbase[p] = xb + (((32 * wn + p * 16 + nrow_l) * FM_XH_STR) + kofs_l) * 2;

        float acc[4][4];
        #pragma unroll
        for (int i = 0; i < 4; i++)
            #pragma unroll
            for (int q = 0; q < 4; q++) acc[i][q] = 0.f;

        #pragma unroll
        for (int kk = 0; kk < 8; kk++) {
            const uint32_t off = kk * 32;
            uint32_t a[4], bf[4][2];
            ldmx4(abase + off, a[0], a[1], a[2], a[3]);
            #pragma unroll
            for (int p = 0; p < 2; p++)
                ldmx4(bbase[p] + off,
                      bf[2 * p][0], bf[2 * p][1], bf[2 * p + 1][0], bf[2 * p + 1][1]);
            #pragma unroll
            for (int nt = 0; nt < 4; nt++) MMA_F16(acc[nt], a, bf[nt]);
        }
        #pragma unroll
        for (int nt = 0; nt < 4; nt++) {
            const int col = 32 * wn + nt * 8 + 2 * tig;
            *(__half2*)&G_h[(16 * wm + gid) * FM_GH_STR + col]     = __floats2half2_rn(acc[nt][0], acc[nt][1]);
            *(__half2*)&G_h[(16 * wm + 8 + gid) * FM_GH_STR + col] = __floats2half2_rn(acc[nt][2], acc[nt][3]);
        }
    }

    // ---- phase 2b: lcb = wl^T @ x (warps 2m x 4n, tile 16x32) ----
    float lacc[4][4];
    const int wm2 = warp >> 2, wn2 = warp & 3;
    {
        #pragma unroll
        for (int i = 0; i < 4; i++)
            #pragma unroll
            for (int q = 0; q < 4; q++) lacc[i][q] = 0.f;

        const uint32_t wlb = smem_u32(wl_h);
        const uint32_t a_addr = wlb +
            (((lane & 7) + 8 * ((lane >> 4) & 1)) * 40 + 16 * wm2 + 8 * ((lane >> 3) & 1)) * 2;
        const int kofB = (lane & 7) + 8 * ((lane >> 3) & 1);
        const int nofB = 8 * (lane >> 4);
        uint32_t b_addr[2];
        #pragma unroll
        for (int p = 0; p < 2; p++)
            b_addr[p] = xb + (kofB * FM_XH_STR + 32 * wn2 + 16 * p + nofB) * 2;

        #pragma unroll
        for (int kk = 0; kk < 4; kk++) {
            uint32_t a[4], bf[4][2];
            ldmx4t(a_addr + kk * 16 * 40 * 2, a[0], a[1], a[2], a[3]);
            #pragma unroll
            for (int p = 0; p < 2; p++)
                ldmx4t(b_addr[p] + kk * 16 * FM_XH_STR * 2,
                       bf[2 * p][0], bf[2 * p][1], bf[2 * p + 1][0], bf[2 * p + 1][1]);
            #pragma unroll
            for (int nt = 0; nt < 4; nt++) MMA_F16(lacc[nt], a, bf[nt]);
        }
    }
    __syncthreads();   // G_h complete; all xs_h reads done (Ls may now alias)

    // ---- phase 3a: stage lcb -> Ls (lacc dies here) ----
    #pragma unroll
    for (int nt = 0; nt < 4; nt++) {
        const int col = 32 * wn2 + nt * 8 + 2 * tig;
        *(float2*)&Ls[(16 * wm2 + gid) * 132 + col]     = make_float2(lacc[nt][0], lacc[nt][1]);
        *(float2*)&Ls[(16 * wm2 + 8 + gid) * 132 + col] = make_float2(lacc[nt][2], lacc[nt][3]);
    }

    // ---- phase 3b: fm = G @ w via mma (warps 4m x 2n, tile 16x16) ----
    float facc[2][4];
    const int wm3 = warp >> 1, wn3 = warp & 1;
    {
        #pragma unroll
        for (int i = 0; i < 2; i++)
            #pragma unroll
            for (int q = 0; q < 4; q++) facc[i][q] = 0.f;

        const uint32_t wb = smem_u32(w_h);
        const uint32_t abase = gb + (((16 * wm3 + (lane & 15)) * FM_GH_STR) + (lane >> 4) * 8) * 2;
        const int kofB = (lane & 7) + 8 * ((lane >> 3) & 1);
        const int nofB = 8 * (lane >> 4);
        const uint32_t b_addr = wb + (kofB * 40 + 16 * wn3 + nofB) * 2;

        #pragma unroll
        for (int kk = 0; kk < 4; kk++) {            // K = 64
            uint32_t a[4], bf[2][2];
            ldmx4(abase + kk * 32, a[0], a[1], a[2], a[3]);
            ldmx4t(b_addr + kk * 16 * 40 * 2, bf[0][0], bf[0][1], bf[1][0], bf[1][1]);
            #pragma unroll
            for (int nt = 0; nt < 2; nt++) MMA_F16(facc[nt], a, bf[nt]);
        }
    }

    // ---- phase 3c: LN stats over facc (padding cols are exact zeros) ----
    {
        float lsum = 0.f, lsq = 0.f;
        #pragma unroll
        for (int nt = 0; nt < 2; nt++)
            #pragma unroll
            for (int q = 0; q < 4; q++) { float v = facc[nt][q]; lsum += v; lsq += v * v; }
        #pragma unroll
        for (int o = 16; o > 0; o >>= 1) {
            lsum += __shfl_xor_sync(0xFFFFFFFFu, lsum, o);
            lsq  += __shfl_xor_sync(0xFFFFFFFFu, lsq,  o);
        }
        if (lane == 0) { red[warp] = lsum; red[8 + warp] = lsq; }
    }
    __syncthreads();   // red + Ls visible
    if (tid == 0) {
        float s = 0.f, q = 0.f;
        #pragma unroll
        for (int i = 0; i < 8; i++) { s += red[i]; q += red[8 + i]; }
        float mu  = s * (1.f / KFM);
        float var = q * (1.f / KFM) - mu * mu;
        float sd  = sqrtf(fmaxf(var, 0.f));
        sd = fminf(fmaxf(sd, 1e-11f), 1e7f);
        red[16] = mu;
        red[17] = 1.f / sd;
    }
    __syncthreads();
    const float mu = red[16], inv = red[17];

    // ---- phase 4a: write fmn (cols >= 24 skipped) ----
    {
        __half* o = g_fmn + (size_t)b * KFM;
        #pragma unroll
        for (int nt = 0; nt < 2; nt++) {
            const int col = 16 * wn3 + nt * 8 + 2 * tig;
            if (col < 24) {
                const int r0 = 16 * wm3 + gid;
                *(__half2*)&o[r0 * 24 + col] =
                    __floats2half2_rn((facc[nt][0] - mu) * inv, (facc[nt][1] - mu) * inv);
                *(__half2*)&o[(r0 + 8) * 24 + col] =
                    __floats2half2_rn((facc[nt][2] - mu) * inv, (facc[nt][3] - mu) * inv);
            }
        }
    }

    // ---- phase 4b: lcb + residual + keras LN -> out rows 32..63 ----
    {
        const float4 g4 = __ldg((const float4*)gamma + lane);
        const float4 bt = __ldg((const float4*)beta  + lane);
        float* ob = out + (size_t)b * NIN * D_;
        #pragma unroll
        for (int i = 0; i < 4; i++) {
            const int sr = warp * 4 + i;          // staged row 0..31
            const int r  = 32 + sr;               // out row
            float4 v  = *(const float4*)&Ls[sr * 132 + lane * 4];
            float4 xr = __ldg((const float4*)(x + (size_t)b * NIN * D_ + r * D_ + lane * 4));
            float4 p = make_float4(v.x + xr.x, v.y + xr.y, v.z + xr.z, v.w + xr.w);
            float s = p.x + p.y + p.z + p.w;
            float q = p.x * p.x + p.y * p.y + p.z * p.z + p.w * p.w;
            #pragma unroll
            for (int o = 16; o > 0; o >>= 1) {
                s += __shfl_xor_sync(0xFFFFFFFFu, s, o);
                q += __shfl_xor_sync(0xFFFFFFFFu, q, o);
            }
            float mean = s * (1.f / 128.f);
            float var  = q * (1.f / 128.f) - mean * mean;
            float invs = rsqrtf(var + 1e-3f);
            float4 o4;
            o4.x = (p.x - mean) * invs * g4.x + bt.x;
            o4.y = (p.y - mean) * invs * g4.y + bt.y;
            o4.z = (p.z - mean) * invs * g4.z + bt.z;
            o4.w = (p.w - mean) * invs * g4.w + bt.w;
            *(float4*)(ob + r * D_ + lane * 4) = o4;
        }
    }
}

// ============================================================================
// k_mm: fp16 mma.sync GEMM (m16n8k16), ldmatrix b16 fragments.
// 128x128x64 CTA tile, 8 warps (2x4), double-buffered cp.async.
// ============================================================================
#define MM_HSTR 72
#define MM_TILEB (128 * MM_HSTR * 2)    // 18432 B per operand tile
#define MM_STGB  (2 * MM_TILEB)         // 36864 B per stage
#define K_MM_SMEM (2 * MM_STGB)         // 73728 B

struct MMCtx {
    uint32_t aoff[4];
    uint32_t boff[2];
    int wr, wc, gid, tig;
};
__device__ __forceinline__ void mm_setup(MMCtx& c, uint32_t sbase, int tid) {
    const int lane = tid & 31, wid = tid >> 5;
    c.wr = wid >> 2; c.wc = wid & 3;
    c.gid = lane >> 2; c.tig = lane & 3;
    #pragma unroll
    for (int mt = 0; mt < 4; mt++)
        c.aoff[mt] = sbase + (((c.wr * 64 + mt * 16 + (lane & 15)) * MM_HSTR) + (lane >> 4) * 8) * 2;
    const int nrow_l = (lane & 7) + 8 * (lane >> 4);
    const int kofs_l = ((lane >> 3) & 1) * 8;
    #pragma unroll
    for (int p = 0; p < 2; p++)
        c.boff[p] = sbase + MM_TILEB + (((c.wc * 32 + p * 16 + nrow_l) * MM_HSTR) + kofs_l) * 2;
}
__device__ __forceinline__ void mm_mainloop(const MMCtx& c, uint32_t sbase, int tid,
                                            const __half* A, const __half* Wt,
                                            int brow, int bcol, int K,
                                            float acc[4][4][4]) {
    auto load_stage = [&](int s, int kc) {
        const uint32_t As = sbase + s * MM_STGB;
        const uint32_t Bs = As + MM_TILEB;
        const __half* Ag = A  + (size_t)brow * K + kc * 64;
        const __half* Bg = Wt + (size_t)bcol * K + kc * 64;
        #pragma unroll
        for (int i = 0; i < 4; i++) {
            int v = tid + i * 256;
            int r = v >> 3, ch = (v & 7) * 8;
            cpasync16(As + (r * MM_HSTR + ch) * 2, Ag + (size_t)r * K + ch);
            cpasync16(Bs + (r * MM_HSTR + ch) * 2, Bg + (size_t)r * K + ch);
        }
    };
    const int NK = K >> 6;
    load_stage(0, 0);
    asm volatile("cp.async.commit_group;");
    for (int kc = 0; kc < NK; kc++) {
        const int buf = kc & 1;
        if (kc + 1 < NK) {
            load_stage(buf ^ 1, kc + 1);
            asm volatile("cp.async.commit_group;");
            asm volatile("cp.async.wait_group 1;");
        } else {
            asm volatile("cp.async.wait_group 0;");
        }
        __syncthreads();
        const uint32_t so = buf * MM_STGB;
        #pragma unroll
        for (int kk = 0; kk < 4; kk++) {
            const uint32_t off = so + kk * 32;
            uint32_t a[4][4], bf[4][2];
            #pragma unroll
            for (int mt = 0; mt < 4; mt++)
                ldmx4(c.aoff[mt] + off, a[mt][0], a[mt][1], a[mt][2], a[mt][3]);
            #pragma unroll
            for (int p = 0; p < 2; p++)
                ldmx4(c.boff[p] + off,
                      bf[2 * p][0], bf[2 * p][1], bf[2 * p + 1][0], bf[2 * p + 1][1]);
            #pragma unroll
            for (int mt = 0; mt < 4; mt++)
                #pragma unroll
                for (int nt = 0; nt < 4; nt++) MMA_F16(acc[mt][nt], a[mt], bf[nt]);
        }
        __syncthreads();
    }
}

__global__ __launch_bounds__(256, 2) void k_mm_relu(const __half* __restrict__ A,
                                                    const __half* __restrict__ Wt,
                                                    __half* __restrict__ C,
                                                    int K, int N)
{
    extern __shared__ char smraw[];
    const uint32_t sbase = smem_u32(smraw);
    const int tid = threadIdx.x;
    const int brow = blockIdx.y * 128, bcol = blockIdx.x * 128;
    MMCtx c; mm_setup(c, sbase, tid);
    float acc[4][4][4];
    #pragma unroll
    for (int i = 0; i < 4; i++)
        #pragma unroll
        for (int j = 0; j < 4; j++)
            #pragma unroll
            for (int q = 0; q < 4; q++) acc[i][j][q] = 0.f;
    mm_mainloop(c, sbase, tid, A, Wt, brow, bcol, K, acc);
    #pragma unroll
    for (int mt = 0; mt < 4; mt++) {
        const int row = brow + c.wr * 64 + mt * 16 + c.gid;
        #pragma unroll
        for (int nt = 0; nt < 4; nt++) {
            const int col = bcol + c.wc * 32 + nt * 8 + 2 * c.tig;
            __half2 h0 = __floats2half2_rn(fmaxf(acc[mt][nt][0], 0.f), fmaxf(acc[mt][nt][1], 0.f));
            __half2 h1 = __floats2half2_rn(fmaxf(acc[mt][nt][2], 0.f), fmaxf(acc[mt][nt][3], 0.f));
            *(__half2*)(C + (size_t)row * N + col)       = h0;
            *(__half2*)(C + (size_t)(row + 8) * N + col) = h1;
        }
    }
}

#define LN_CSTR 132

__global__ __launch_bounds__(256, 2) void k_mm_ln(const __half* __restrict__ A,
                                                  const __half* __restrict__ Wt,
                                                  const float* __restrict__ x,
                                                  const float* __restrict__ gamma,
                                                  const float* __restrict__ beta,
                                                  float* __restrict__ out,
                                                  int K)
{
    extern __shared__ char smraw[];
    float* S = (float*)smraw;
    const uint32_t sbase = smem_u32(smraw);
    const int tid = threadIdx.x, lane = tid & 31, wid = tid >> 5;
    const int brow = blockIdx.y * 128, bcol = blockIdx.x * 128;
    MMCtx c; mm_setup(c, sbase, tid);
    float acc[4][4][4];
    #pragma unroll
    for (int i = 0; i < 4; i++)
        #pragma unroll
        for (int j = 0; j < 4; j++)
            #pragma unroll
            for (int q = 0; q < 4; q++) acc[i][j][q] = 0.f;
    mm_mainloop(c, sbase, tid, A, Wt, brow, bcol, K, acc);

    #pragma unroll
    for (int mt = 0; mt < 4; mt++) {
        const int r0 = c.wr * 64 + mt * 16 + c.gid;
        #pragma unroll
        for (int nt = 0; nt < 4; nt++) {
            const int col = c.wc * 32 + nt * 8 + 2 * c.tig;
            *(float2*)&S[r0 * LN_CSTR + col]       = make_float2(acc[mt][nt][0], acc[mt][nt][1]);
            *(float2*)&S[(r0 + 8) * LN_CSTR + col] = make_float2(acc[mt][nt][2], acc[mt][nt][3]);
        }
    }
    __syncthreads();

    const float4 g4 = __ldg((const float4*)gamma + lane);
    const float4 bt = __ldg((const float4*)beta  + lane);

    #pragma unroll
    for (int rr = 0; rr < 16; rr++) {
        const int r = wid * 16 + rr;
        const int b = brow + r;
        float4 v = *(const float4*)&S[r * LN_CSTR + lane * 4];
        float4 xr = __ldg((const float4*)(x + (size_t)b * NIN * D_ + bcol + lane * 4));
        float4 p = make_float4(v.x + xr.x, v.y + xr.y, v.z + xr.z, v.w + xr.w);
        float s = p.x + p.y + p.z + p.w;
        float q = p.x * p.x + p.y * p.y + p.z * p.z + p.w * p.w;
        #pragma unroll
        for (int o = 16; o > 0; o >>= 1) {
            s += __shfl_xor_sync(0xFFFFFFFFu, s, o);
            q += __shfl_xor_sync(0xFFFFFFFFu, q, o);
        }
        float mean = s * (1.f / 128.f);
        float var  = q * (1.f / 128.f) - mean * mean;
        float inv  = rsqrtf(var + 1e-3f);
        float4 o4;
        o4.x = (p.x - mean) * inv * g4.x + bt.x;
        o4.y = (p.y - mean) * inv * g4.y + bt.y;
        o4.z = (p.z - mean) * inv * g4.z + bt.z;
        o4.w = (p.w - mean) * inv * g4.w + bt.w;
        *(float4*)(out + (size_t)b * NIN * D_ + bcol + lane * 4) = o4;
    }
}

// ============================================================================
extern "C" void kernel_launch(void* const* d_in, const int* in_sizes, int n_in,
                              void* d_out, int out_size)
{
    const float* x      = (const float*)d_in[0];
    // d_in[1] = noise: only enters via 1e-10*extra -> numerically irrelevant
    const float* w_lcb  = (const float*)d_in[2];
    const float* w_rank = (const float*)d_in[3];
    const float* w1     = (const float*)d_in[4];
    const float* w2     = (const float*)d_in[5];
    const float* w3     = (const float*)d_in[6];
    const float* gamma  = (const float*)d_in[7];
    const float* beta   = (const float*)d_in[8];
    float* out = (float*)d_out;

    __half *fmn, *h1, *h2, *w1t, *w2t, *w3t;
    cudaGetSymbolAddress((void**)&fmn, g_fmn);
    cudaGetSymbolAddress((void**)&h1,  g_h1);
    cudaGetSymbolAddress((void**)&h2,  g_h2);
    cudaGetSymbolAddress((void**)&w1t, g_w1t);
    cudaGetSymbolAddress((void**)&w2t, g_w2t);
    cudaGetSymbolAddress((void**)&w3t, g_w3t);

    cudaFuncSetAttribute(k_mm_relu, cudaFuncAttributeMaxDynamicSharedMemorySize, K_MM_SMEM);
    cudaFuncSetAttribute(k_mm_ln,   cudaFuncAttributeMaxDynamicSharedMemorySize, K_MM_SMEM);
    cudaFuncSetAttribute(k_fm,      cudaFuncAttributeMaxDynamicSharedMemorySize, FM_SMEM);

    k_tr<<<dim3(HID / 32, KFM / 32), dim3(16, 16)>>>(w1, w1t, KFM, HID);
    k_tr<<<dim3(HID / 32, HID / 32), dim3(16, 16)>>>(w2, w2t, HID, HID);
    k_tr<<<dim3(N3  / 32, HID / 32), dim3(16, 16)>>>(w3, w3t, HID, N3);

    k_fm<<<B_, 256, FM_SMEM>>>(x, w_rank, w_lcb, gamma, beta, out);

    k_mm_relu<<<dim3(HID / 128, B_ / 128), 256, K_MM_SMEM>>>(fmn, w1t, h1, KFM, HID);
    k_mm_relu<<<dim3(HID / 128, B_ / 128), 256, K_MM_SMEM>>>(h1,  w2t, h2, HID, HID);
    k_mm_ln  <<<dim3(N3  / 128, B_ / 128), 256, K_MM_SMEM>>>(h2,  w3t, x, gamma, beta, out, HID);
}

// round 13
// speedup vs baseline: 1.1598x; 1.0419x over previous
#include <cuda_runtime.h>
#include <cuda_fp16.h>
#include <cstdint>
#include <cstddef>

#define B_   2048
#define NIN  64
#define D_   128
#define RANK 24
#define KFM  1536   // NIN*RANK
#define HID  1024
#define N3   4096   // N_FMB*D

// ---- scratch (static device globals; no runtime allocation) ----
__device__ __half g_fmn[B_ * KFM];     // normalized FM features (half)
__device__ __half g_h1 [B_ * HID];
__device__ __half g_h2 [B_ * HID];
__device__ __half g_w1t[HID * KFM];    // w^T [N,K] half
__device__ __half g_w2t[HID * HID];
__device__ __half g_w3t[N3  * HID];

// ============================================================================
// helpers
// ============================================================================
__device__ __forceinline__ uint32_t smem_u32(const void* p) {
    uint32_t a;
    asm("{ .reg .u64 t; cvta.to.shared.u64 t, %1; cvt.u32.u64 %0, t; }" : "=r"(a) : "l"(p));
    return a;
}
__device__ __forceinline__ void cpasync16(uint32_t dst, const void* src) {
    asm volatile("cp.async.cg.shared.global [%0], [%1], 16;" :: "r"(dst), "l"(src));
}
__device__ __forceinline__ void ldmx4(uint32_t addr, uint32_t& r0, uint32_t& r1,
                                      uint32_t& r2, uint32_t& r3) {
    asm volatile("ldmatrix.sync.aligned.m8n8.x4.shared.b16 {%0,%1,%2,%3}, [%4];"
                 : "=r"(r0), "=r"(r1), "=r"(r2), "=r"(r3) : "r"(addr));
}
__device__ __forceinline__ void ldmx4t(uint32_t addr, uint32_t& r0, uint32_t& r1,
                                       uint32_t& r2, uint32_t& r3) {
    asm volatile("ldmatrix.sync.aligned.m8n8.x4.trans.shared.b16 {%0,%1,%2,%3}, [%4];"
                 : "=r"(r0), "=r"(r1), "=r"(r2), "=r"(r3) : "r"(addr));
}
// fp16 mma with fp32 accumulators: m16n8k16
#define MMA_F16(acc, a, b)                                                      \
    asm volatile("mma.sync.aligned.m16n8k16.row.col.f32.f16.f16.f32 "           \
        "{%0,%1,%2,%3}, {%4,%5,%6,%7}, {%8,%9}, {%0,%1,%2,%3};"                 \
        : "+f"((acc)[0]), "+f"((acc)[1]), "+f"((acc)[2]), "+f"((acc)[3])        \
        : "r"((a)[0]), "r"((a)[1]), "r"((a)[2]), "r"((a)[3]),                   \
          "r"((b)[0]), "r"((b)[1]))

// ============================================================================
// k_tr3: all three weight transposes in ONE launch.
//   w1 [1536,1024] -> tiles 0..1535; w2 [1024,1024] -> 1536..2559;
//   w3 [1024,4096] -> 2560..6655.  Dst[N,K] = half(Src[K,N]^T).
// ============================================================================
__global__ __launch_bounds__(256) void k_tr3(const float* __restrict__ w1,
                                             const float* __restrict__ w2,
                                             const float* __restrict__ w3,
                                             __half* __restrict__ o1,
                                             __half* __restrict__ o2,
                                             __half* __restrict__ o3)
{
    __shared__ float t[32][33];
    const int bid = blockIdx.x;
    const float* S;
    __half* Dst;
    int K, N, tt;
    if (bid < 1536)      { S = w1; Dst = o1; K = KFM; N = HID; tt = bid; }
    else if (bid < 2560) { S = w2; Dst = o2; K = HID; N = HID; tt = bid - 1536; }
    else                 { S = w3; Dst = o3; K = HID; N = N3;  tt = bid - 2560; }
    const int nb = N / 32;
    const int k0 = (tt / nb) * 32, n0 = (tt % nb) * 32;
    const int tx = threadIdx.x, ty = threadIdx.y;   // 16 x 16
    #pragma unroll
    for (int i = 0; i < 2; i++) {
        float2 v = *(const float2*)&S[(size_t)(k0 + ty + i * 16) * N + n0 + 2 * tx];
        t[ty + i * 16][2 * tx]     = v.x;
        t[ty + i * 16][2 * tx + 1] = v.y;
    }
    __syncthreads();
    #pragma unroll
    for (int i = 0; i < 2; i++) {
        const int n = n0 + ty + i * 16;
        __half2 h = __floats2half2_rn(t[2 * tx][ty + i * 16], t[2 * tx + 1][ty + i * 16]);
        *(__half2*)&Dst[(size_t)n * K + k0 + 2 * tx] = h;
    }
}

// ============================================================================
// k_fm: per-batch FM block, ALL matmuls on fp16 mma (R12, unchanged).
// ============================================================================
#define FM_XH_STR 136
#define FM_GH_STR 72
#define FM_B_GH   128
#define FM_B_WH   (FM_B_GH + 64 * FM_GH_STR * 2)     // 9344
#define FM_B_WLH  (FM_B_WH + 64 * 40 * 2)            // 14464
#define FM_B_XH   (FM_B_WLH + 64 * 40 * 2)           // 19584
#define FM_SMEM   (FM_B_XH + 64 * FM_XH_STR * 2)     // 36992 B

__global__ __launch_bounds__(256, 4) void k_fm(const float* __restrict__ x,
                                               const float* __restrict__ wr,
                                               const float* __restrict__ wl,
                                               const float* __restrict__ gamma,
                                               const float* __restrict__ beta,
                                               float* __restrict__ out)
{
    extern __shared__ float Sf[];
    float*  red  = Sf;                                     // 32 floats
    __half* G_h  = (__half*)((char*)Sf + FM_B_GH);         // 64 x 72
    __half* w_h  = (__half*)((char*)Sf + FM_B_WH);         // 64 x 40 (cols 24-31 zero)
    __half* wl_h = (__half*)((char*)Sf + FM_B_WLH);        // 64 x 40
    __half* xs_h = (__half*)((char*)Sf + FM_B_XH);         // 64 x 136
    float*  Ls   = (float*)((char*)Sf + FM_B_XH);          // 32 x 132 (aliases xs_h)

    const int b = blockIdx.x, tid = threadIdx.x;
    const int lane = tid & 31, warp = tid >> 5;
    const int gid = lane >> 2, tig = lane & 3;

    // ---- phase 1: loads ----
    {
        const float4* xg = (const float4*)(x + (size_t)b * NIN * D_);
        #pragma unroll
        for (int i = 0; i < 8; i++) {
            int v = tid + i * 256;
            float4 t = xg[v];
            int n = v >> 5, d0 = (v & 31) * 4;
            *(__half2*)&xs_h[n * FM_XH_STR + d0]     = __floats2half2_rn(t.x, t.y);
            *(__half2*)&xs_h[n * FM_XH_STR + d0 + 2] = __floats2half2_rn(t.z, t.w);
        }
        const float4* wg = (const float4*)wr;
        #pragma unroll
        for (int i = 0; i < 2; i++) {
            int idx = tid + i * 256;
            if (idx < 384) {
                float4 t = wg[idx];
                int m = idx / 6, j0 = (idx % 6) * 4;
                *(__half2*)&w_h[m * 40 + j0]     = __floats2half2_rn(t.x, t.y);
                *(__half2*)&w_h[m * 40 + j0 + 2] = __floats2half2_rn(t.z, t.w);
            }
        }
        {
            int row = tid >> 2, c = (tid & 3) * 2;
            *(__half2*)&w_h[row * 40 + 24 + c] = __floats2half2_rn(0.f, 0.f);
        }
        const float4* wlg = (const float4*)wl;
        #pragma unroll
        for (int i = 0; i < 2; i++) {
            int idx = tid + i * 256;
            float4 t = wlg[idx];
            int nn = idx >> 3, m0 = (idx & 7) * 4;
            *(__half2*)&wl_h[nn * 40 + m0]     = __floats2half2_rn(t.x, t.y);
            *(__half2*)&wl_h[nn * 40 + m0 + 2] = __floats2half2_rn(t.z, t.w);
        }
    }
    __syncthreads();

    const uint32_t xb = smem_u32(xs_h);
    const uint32_t gb = smem_u32(G_h);

    // ---- phase 2a: G = x @ x^T (warps 4m x 2n, tile 16x32), store HALF ----
    {
        const int wm = warp >> 1, wn = warp & 1;
        const uint32_t abase = xb + (((16 * wm + (lane & 15)) * FM_XH_STR) + (lane >> 4) * 8) * 2;
        const int nrow_l = (lane & 7) + 8 * (lane >> 4);
        const int kofs_l = ((lane >> 3) & 1) * 8;
        uint32_t bbase[2];
        #pragma unroll
        for (int p = 0; p < 2; p++)
            bbase[p] = xb + (((32 * wn + p * 16 + nrow_l) * FM_XH_STR) + kofs_l) * 2;

        float acc[4][4];
        #pragma unroll
        for (int i = 0; i < 4; i++)
            #pragma unroll
            for (int q = 0; q < 4; q++) acc[i][q] = 0.f;

        #pragma unroll
        for (int kk = 0; kk < 8; kk++) {
            const uint32_t off = kk * 32;
            uint32_t a[4], bf[4][2];
            ldmx4(abase + off, a[0], a[1], a[2], a[3]);
            #pragma unroll
            for (int p = 0; p < 2; p++)
                ldmx4(bbase[p] + off,
                      bf[2 * p][0], bf[2 * p][1], bf[2 * p + 1][0], bf[2 * p + 1][1]);
            #pragma unroll
            for (int nt = 0; nt < 4; nt++) MMA_F16(acc[nt], a, bf[nt]);
        }
        #pragma unroll
        for (int nt = 0; nt < 4; nt++) {
            const int col = 32 * wn + nt * 8 + 2 * tig;
            *(__half2*)&G_h[(16 * wm + gid) * FM_GH_STR + col]     = __floats2half2_rn(acc[nt][0], acc[nt][1]);
            *(__half2*)&G_h[(16 * wm + 8 + gid) * FM_GH_STR + col] = __floats2half2_rn(acc[nt][2], acc[nt][3]);
        }
    }

    // ---- phase 2b: lcb = wl^T @ x (warps 2m x 4n, tile 16x32) ----
    float lacc[4][4];
    const int wm2 = warp >> 2, wn2 = warp & 3;
    {
        #pragma unroll
        for (int i = 0; i < 4; i++)
            #pragma unroll
            for (int q = 0; q < 4; q++) lacc[i][q] = 0.f;

        const uint32_t wlb = smem_u32(wl_h);
        const uint32_t a_addr = wlb +
            (((lane & 7) + 8 * ((lane >> 4) & 1)) * 40 + 16 * wm2 + 8 * ((lane >> 3) & 1)) * 2;
        const int kofB = (lane & 7) + 8 * ((lane >> 3) & 1);
        const int nofB = 8 * (lane >> 4);
        uint32_t b_addr[2];
        #pragma unroll
        for (int p = 0; p < 2; p++)
            b_addr[p] = xb + (kofB * FM_XH_STR + 32 * wn2 + 16 * p + nofB) * 2;

        #pragma unroll
        for (int kk = 0; kk < 4; kk++) {
            uint32_t a[4], bf[4][2];
            ldmx4t(a_addr + kk * 16 * 40 * 2, a[0], a[1], a[2], a[3]);
            #pragma unroll
            for (int p = 0; p < 2; p++)
                ldmx4t(b_addr[p] + kk * 16 * FM_XH_STR * 2,
                       bf[2 * p][0], bf[2 * p][1], bf[2 * p + 1][0], bf[2 * p + 1][1]);
            #pragma unroll
            for (int nt = 0; nt < 4; nt++) MMA_F16(lacc[nt], a, bf[nt]);
        }
    }
    __syncthreads();   // G_h complete; all xs_h reads done (Ls may now alias)

    // ---- phase 3a: stage lcb -> Ls ----
    #pragma unroll
    for (int nt = 0; nt < 4; nt++) {
        const int col = 32 * wn2 + nt * 8 + 2 * tig;
        *(float2*)&Ls[(16 * wm2 + gid) * 132 + col]     = make_float2(lacc[nt][0], lacc[nt][1]);
        *(float2*)&Ls[(16 * wm2 + 8 + gid) * 132 + col] = make_float2(lacc[nt][2], lacc[nt][3]);
    }

    // ---- phase 3b: fm = G @ w via mma (warps 4m x 2n, tile 16x16) ----
    float facc[2][4];
    const int wm3 = warp >> 1, wn3 = warp & 1;
    {
        #pragma unroll
        for (int i = 0; i < 2; i++)
            #pragma unroll
            for (int q = 0; q < 4; q++) facc[i][q] = 0.f;

        const uint32_t wb = smem_u32(w_h);
        const uint32_t abase = gb + (((16 * wm3 + (lane & 15)) * FM_GH_STR) + (lane >> 4) * 8) * 2;
        const int kofB = (lane & 7) + 8 * ((lane >> 3) & 1);
        const int nofB = 8 * (lane >> 4);
        const uint32_t b_addr = wb + (kofB * 40 + 16 * wn3 + nofB) * 2;

        #pragma unroll
        for (int kk = 0; kk < 4; kk++) {            // K = 64
            uint32_t a[4], bf[2][2];
            ldmx4(abase + kk * 32, a[0], a[1], a[2], a[3]);
            ldmx4t(b_addr + kk * 16 * 40 * 2, bf[0][0], bf[0][1], bf[1][0], bf[1][1]);
            #pragma unroll
            for (int nt = 0; nt < 2; nt++) MMA_F16(facc[nt], a, bf[nt]);
        }
    }

    // ---- phase 3c: LN stats over facc (padding cols exact zeros) ----
    {
        float lsum = 0.f, lsq = 0.f;
        #pragma unroll
        for (int nt = 0; nt < 2; nt++)
            #pragma unroll
            for (int q = 0; q < 4; q++) { float v = facc[nt][q]; lsum += v; lsq += v * v; }
        #pragma unroll
        for (int o = 16; o > 0; o >>= 1) {
            lsum += __shfl_xor_sync(0xFFFFFFFFu, lsum, o);
            lsq  += __shfl_xor_sync(0xFFFFFFFFu, lsq,  o);
        }
        if (lane == 0) { red[warp] = lsum; red[8 + warp] = lsq; }
    }
    __syncthreads();
    if (tid == 0) {
        float s = 0.f, q = 0.f;
        #pragma unroll
        for (int i = 0; i < 8; i++) { s += red[i]; q += red[8 + i]; }
        float mu  = s * (1.f / KFM);
        float var = q * (1.f / KFM) - mu * mu;
        float sd  = sqrtf(fmaxf(var, 0.f));
        sd = fminf(fmaxf(sd, 1e-11f), 1e7f);
        red[16] = mu;
        red[17] = 1.f / sd;
    }
    __syncthreads();
    const float mu = red[16], inv = red[17];

    // ---- phase 4a: write fmn ----
    {
        __half* o = g_fmn + (size_t)b * KFM;
        #pragma unroll
        for (int nt = 0; nt < 2; nt++) {
            const int col = 16 * wn3 + nt * 8 + 2 * tig;
            if (col < 24) {
                const int r0 = 16 * wm3 + gid;
                *(__half2*)&o[r0 * 24 + col] =
                    __floats2half2_rn((facc[nt][0] - mu) * inv, (facc[nt][1] - mu) * inv);
                *(__half2*)&o[(r0 + 8) * 24 + col] =
                    __floats2half2_rn((facc[nt][2] - mu) * inv, (facc[nt][3] - mu) * inv);
            }
        }
    }

    // ---- phase 4b: lcb + residual + keras LN -> out rows 32..63 ----
    {
        const float4 g4 = __ldg((const float4*)gamma + lane);
        const float4 bt = __ldg((const float4*)beta  + lane);
        float* ob = out + (size_t)b * NIN * D_;
        #pragma unroll
        for (int i = 0; i < 4; i++) {
            const int sr = warp * 4 + i;
            const int r  = 32 + sr;
            float4 v  = *(const float4*)&Ls[sr * 132 + lane * 4];
            float4 xr = __ldg((const float4*)(x + (size_t)b * NIN * D_ + r * D_ + lane * 4));
            float4 p = make_float4(v.x + xr.x, v.y + xr.y, v.z + xr.z, v.w + xr.w);
            float s = p.x + p.y + p.z + p.w;
            float q = p.x * p.x + p.y * p.y + p.z * p.z + p.w * p.w;
            #pragma unroll
            for (int o = 16; o > 0; o >>= 1) {
                s += __shfl_xor_sync(0xFFFFFFFFu, s, o);
                q += __shfl_xor_sync(0xFFFFFFFFu, q, o);
            }
            float mean = s * (1.f / 128.f);
            float var  = q * (1.f / 128.f) - mean * mean;
            float invs = rsqrtf(var + 1e-3f);
            float4 o4;
            o4.x = (p.x - mean) * invs * g4.x + bt.x;
            o4.y = (p.y - mean) * invs * g4.y + bt.y;
            o4.z = (p.z - mean) * invs * g4.z + bt.z;
            o4.w = (p.w - mean) * invs * g4.w + bt.w;
            *(float4*)(ob + r * D_ + lane * 4) = o4;
        }
    }
}

// ============================================================================
// k_mm: fp16 mma.sync GEMM, 128x128x64 CTA tile, 8 warps (2x4).
// THREE-stage cp.async pipeline, ONE __syncthreads per K-chunk.
// ============================================================================
#define MM_HSTR 72
#define MM_TILEB (128 * MM_HSTR * 2)    // 18432 B per operand tile
#define MM_STGB  (2 * MM_TILEB)         // 36864 B per stage
#define MM_STAGES 3
#define K_MM_SMEM (MM_STAGES * MM_STGB) // 110592 B

struct MMCtx {
    uint32_t aoff[4];
    uint32_t boff[2];
    int wr, wc, gid, tig;
};
__device__ __forceinline__ void mm_setup(MMCtx& c, uint32_t sbase, int tid) {
    const int lane = tid & 31, wid = tid >> 5;
    c.wr = wid >> 2; c.wc = wid & 3;
    c.gid = lane >> 2; c.tig = lane & 3;
    #pragma unroll
    for (int mt = 0; mt < 4; mt++)
        c.aoff[mt] = sbase + (((c.wr * 64 + mt * 16 + (lane & 15)) * MM_HSTR) + (lane >> 4) * 8) * 2;
    const int nrow_l = (lane & 7) + 8 * (lane >> 4);
    const int kofs_l = ((lane >> 3) & 1) * 8;
    #pragma unroll
    for (int p = 0; p < 2; p++)
        c.boff[p] = sbase + MM_TILEB + (((c.wc * 32 + p * 16 + nrow_l) * MM_HSTR) + kofs_l) * 2;
}
__device__ __forceinline__ void mm_mainloop(const MMCtx& c, uint32_t sbase, int tid,
                                            const __half* A, const __half* Wt,
                                            int brow, int bcol, int K,
                                            float acc[4][4][4]) {
    auto load_stage = [&](int s, int kc) {
        const uint32_t As = sbase + s * MM_STGB;
        const uint32_t Bs = As + MM_TILEB;
        const __half* Ag = A  + (size_t)brow * K + kc * 64;
        const __half* Bg = Wt + (size_t)bcol * K + kc * 64;
        #pragma unroll
        for (int i = 0; i < 4; i++) {
            int v = tid + i * 256;
            int r = v >> 3, ch = (v & 7) * 8;
            cpasync16(As + (r * MM_HSTR + ch) * 2, Ag + (size_t)r * K + ch);
            cpasync16(Bs + (r * MM_HSTR + ch) * 2, Bg + (size_t)r * K + ch);
        }
        asm volatile("cp.async.commit_group;");
    };
    const int NK = K >> 6;            // >= 16 always
    load_stage(0, 0);
    load_stage(1, 1);

    int slot = 0;
    for (int kc = 0; kc < NK; kc++) {
        if (kc + 1 < NK) asm volatile("cp.async.wait_group 1;");
        else             asm volatile("cp.async.wait_group 0;");
        __syncthreads();              // chunk kc resident; prior compute done

        if (kc + 2 < NK) {
            int ns = slot + 2; if (ns >= MM_STAGES) ns -= MM_STAGES;
            load_stage(ns, kc + 2);   // slot freed by chunk kc-1
        }

        const uint32_t so = slot * MM_STGB;
        #pragma unroll
        for (int kk = 0; kk < 4; kk++) {
            const uint32_t off = so + kk * 32;
            uint32_t a[4][4], bf[4][2];
            #pragma unroll
            for (int mt = 0; mt < 4; mt++)
                ldmx4(c.aoff[mt] + off, a[mt][0], a[mt][1], a[mt][2], a[mt][3]);
            #pragma unroll
            for (int p = 0; p < 2; p++)
                ldmx4(c.boff[p] + off,
                      bf[2 * p][0], bf[2 * p][1], bf[2 * p + 1][0], bf[2 * p + 1][1]);
            #pragma unroll
            for (int mt = 0; mt < 4; mt++)
                #pragma unroll
                for (int nt = 0; nt < 4; nt++) MMA_F16(acc[mt][nt], a[mt], bf[nt]);
        }
        if (++slot == MM_STAGES) slot = 0;
    }
    __syncthreads();                  // protect smem reuse by epilogue
}

__global__ __launch_bounds__(256, 2) void k_mm_relu(const __half* __restrict__ A,
                                                    const __half* __restrict__ Wt,
                                                    __half* __restrict__ C,
                                                    int K, int N)
{
    extern __shared__ char smraw[];
    const uint32_t sbase = smem_u32(smraw);
    const int tid = threadIdx.x;
    const int brow = blockIdx.y * 128, bcol = blockIdx.x * 128;
    MMCtx c; mm_setup(c, sbase, tid);
    float acc[4][4][4];
    #pragma unroll
    for (int i = 0; i < 4; i++)
        #pragma unroll
        for (int j = 0; j < 4; j++)
            #pragma unroll
            for (int q = 0; q < 4; q++) acc[i][j][q] = 0.f;
    mm_mainloop(c, sbase, tid, A, Wt, brow, bcol, K, acc);
    #pragma unroll
    for (int mt = 0; mt < 4; mt++) {
        const int row = brow + c.wr * 64 + mt * 16 + c.gid;
        #pragma unroll
        for (int nt = 0; nt < 4; nt++) {
            const int col = bcol + c.wc * 32 + nt * 8 + 2 * c.tig;
            __half2 h0 = __floats2half2_rn(fmaxf(acc[mt][nt][0], 0.f), fmaxf(acc[mt][nt][1], 0.f));
            __half2 h1 = __floats2half2_rn(fmaxf(acc[mt][nt][2], 0.f), fmaxf(acc[mt][nt][3], 0.f));
            *(__half2*)(C + (size_t)row * N + col)       = h0;
            *(__half2*)(C + (size_t)(row + 8) * N + col) = h1;
        }
    }
}

#define LN_CSTR 132

__global__ __launch_bounds__(256, 2) void k_mm_ln(const __half* __restrict__ A,
                                                  const __half* __restrict__ Wt,
                                                  const float* __restrict__ x,
                                                  const float* __restrict__ gamma,
                                                  const float* __restrict__ beta,
                                                  float* __restrict__ out,
                                                  int K)
{
    extern __shared__ char smraw[];
    float* S = (float*)smraw;
    const uint32_t sbase = smem_u32(smraw);
    const int tid = threadIdx.x, lane = tid & 31, wid = tid >> 5;
    const int brow = blockIdx.y * 128, bcol = blockIdx.x * 128;
    MMCtx c; mm_setup(c, sbase, tid);
    float acc[4][4][4];
    #pragma unroll
    for (int i = 0; i < 4; i++)
        #pragma unroll
        for (int j = 0; j < 4; j++)
            #pragma unroll
            for (int q = 0; q < 4; q++) acc[i][j][q] = 0.f;
    mm_mainloop(c, sbase, tid, A, Wt, brow, bcol, K, acc);

    // stage acc -> smem (mainloop done; 128*132*4 = 67584 <= 110592)
    #pragma unroll
    for (int mt = 0; mt < 4; mt++) {
        const int r0 = c.wr * 64 + mt * 16 + c.gid;
        #pragma unroll
        for (int nt = 0; nt < 4; nt++) {
            const int col = c.wc * 32 + nt * 8 + 2 * c.tig;
            *(float2*)&S[r0 * LN_CSTR + col]       = make_float2(acc[mt][nt][0], acc[mt][nt][1]);
            *(float2*)&S[(r0 + 8) * LN_CSTR + col] = make_float2(acc[mt][nt][2], acc[mt][nt][3]);
        }
    }
    __syncthreads();

    const float4 g4 = __ldg((const float4*)gamma + lane);
    const float4 bt = __ldg((const float4*)beta  + lane);

    #pragma unroll
    for (int rr = 0; rr < 16; rr++) {
        const int r = wid * 16 + rr;
        const int b = brow + r;
        float4 v = *(const float4*)&S[r * LN_CSTR + lane * 4];
        float4 xr = __ldg((const float4*)(x + (size_t)b * NIN * D_ + bcol + lane * 4));
        float4 p = make_float4(v.x + xr.x, v.y + xr.y, v.z + xr.z, v.w + xr.w);
        float s = p.x + p.y + p.z + p.w;
        float q = p.x * p.x + p.y * p.y + p.z * p.z + p.w * p.w;
        #pragma unroll
        for (int o = 16; o > 0; o >>= 1) {
            s += __shfl_xor_sync(0xFFFFFFFFu, s, o);
            q += __shfl_xor_sync(0xFFFFFFFFu, q, o);
        }
        float mean = s * (1.f / 128.f);
        float var  = q * (1.f / 128.f) - mean * mean;
        float inv  = rsqrtf(var + 1e-3f);
        float4 o4;
        o4.x = (p.x - mean) * inv * g4.x + bt.x;
        o4.y = (p.y - mean) * inv * g4.y + bt.y;
        o4.z = (p.z - mean) * inv * g4.z + bt.z;
        o4.w = (p.w - mean) * inv * g4.w + bt.w;
        *(float4*)(out + (size_t)b * NIN * D_ + bcol + lane * 4) = o4;
    }
}

// ============================================================================
extern "C" void kernel_launch(void* const* d_in, const int* in_sizes, int n_in,
                              void* d_out, int out_size)
{
    const float* x      = (const float*)d_in[0];
    // d_in[1] = noise: only enters via 1e-10*extra -> numerically irrelevant
    const float* w_lcb  = (const float*)d_in[2];
    const float* w_rank = (const float*)d_in[3];
    const float* w1     = (const float*)d_in[4];
    const float* w2     = (const float*)d_in[5];
    const float* w3     = (const float*)d_in[6];
    const float* gamma  = (const float*)d_in[7];
    const float* beta   = (const float*)d_in[8];
    float* out = (float*)d_out;

    __half *fmn, *h1, *h2, *w1t, *w2t, *w3t;
    cudaGetSymbolAddress((void**)&fmn, g_fmn);
    cudaGetSymbolAddress((void**)&h1,  g_h1);
    cudaGetSymbolAddress((void**)&h2,  g_h2);
    cudaGetSymbolAddress((void**)&w1t, g_w1t);
    cudaGetSymbolAddress((void**)&w2t, g_w2t);
    cudaGetSymbolAddress((void**)&w3t, g_w3t);

    cudaFuncSetAttribute(k_mm_relu, cudaFuncAttributeMaxDynamicSharedMemorySize, K_MM_SMEM);
    cudaFuncSetAttribute(k_mm_ln,   cudaFuncAttributeMaxDynamicSharedMemorySize, K_MM_SMEM);
    cudaFuncSetAttribute(k_fm,      cudaFuncAttributeMaxDynamicSharedMemorySize, FM_SMEM);

    k_tr3<<<6656, dim3(16, 16)>>>(w1, w2, w3, w1t, w2t, w3t);

    k_fm<<<B_, 256, FM_SMEM>>>(x, w_rank, w_lcb, gamma, beta, out);

    k_mm_relu<<<dim3(HID / 128, B_ / 128), 256, K_MM_SMEM>>>(fmn, w1t, h1, KFM, HID);
    k_mm_relu<<<dim3(HID / 128, B_ / 128), 256, K_MM_SMEM>>>(h1,  w2t, h2, HID, HID);
    k_mm_ln  <<<dim3(N3  / 128, B_ / 128), 256, K_MM_SMEM>>>(h2,  w3t, x, gamma, beta, out, HID);
}